// round 5
// baseline (speedup 1.0000x reference)
#include <cuda_runtime.h>
#include <math.h>

// Problem constants
#define B_   2
#define S_   2048
#define HID_ 2560
#define H_   32
#define KV_  8
#define D_   80
#define G_   4
#define BS_  (B_*S_)      // 4096 total rows

// Scratch (device globals)
__device__ float g_Q[(size_t)BS_ * H_ * D_];
__device__ float g_K[(size_t)BS_ * KV_ * D_];
__device__ float g_V[(size_t)BS_ * KV_ * D_];
__device__ float g_ctx[(size_t)BS_ * H_ * D_];
__device__ float g_hs_r[(size_t)BS_ * HID_];
__device__ float g_Wq_r[(size_t)HID_ * H_ * D_];
__device__ float g_Wk_r[(size_t)HID_ * KV_ * D_];
__device__ float g_Wv_r[(size_t)HID_ * KV_ * D_];
__device__ float g_Wo_r[(size_t)H_ * D_ * HID_];

// ---------------------------------------------------------------------------
// Helpers
// ---------------------------------------------------------------------------
__device__ __forceinline__ unsigned smem_u32(const void* p) {
    return (unsigned)__cvta_generic_to_shared(p);
}
__device__ __forceinline__ void cp_async16(unsigned dst, const void* src) {
    asm volatile("cp.async.cg.shared.global [%0], [%1], 16;\n"
                 :: "r"(dst), "l"(src));
}
#define CP_COMMIT() asm volatile("cp.async.commit_group;\n" ::: "memory")

__device__ __forceinline__ float tf32_rna(float v) {
    unsigned u;
    asm("cvt.rna.tf32.f32 %0, %1;" : "=r"(u) : "f"(v));
    return __uint_as_float(u);
}

__device__ __forceinline__ void mma_tf32(float* c, const unsigned* a, const unsigned* b) {
    asm volatile(
        "mma.sync.aligned.m16n8k8.row.col.f32.tf32.tf32.f32 "
        "{%0,%1,%2,%3}, {%4,%5,%6,%7}, {%8,%9}, {%0,%1,%2,%3};\n"
        : "+f"(c[0]), "+f"(c[1]), "+f"(c[2]), "+f"(c[3])
        : "r"(a[0]), "r"(a[1]), "r"(a[2]), "r"(a[3]), "r"(b[0]), "r"(b[1]));
}

// ---------------------------------------------------------------------------
// TF32 RNA rounding pre-pass
// ---------------------------------------------------------------------------
__global__ void round_tf32(const float4* __restrict__ in,
                           float4* __restrict__ out, int n4)
{
    int i = blockIdx.x * blockDim.x + threadIdx.x;
    if (i < n4) {
        float4 v = in[i];
        v.x = tf32_rna(v.x); v.y = tf32_rna(v.y);
        v.z = tf32_rna(v.z); v.w = tf32_rna(v.w);
        out[i] = v;
    }
}

// ---------------------------------------------------------------------------
// TF32 mma.sync GEMM, 3-stage cp.async pipeline.
// BM=128, BK=16, 256 threads, 8 warps = 2(m) x 4(n); warp tile 64 x (BN/4).
// A smem [m][k] stride 20; B smem [k][n] stride BN+8. Both conflict-free.
// ---------------------------------------------------------------------------
#define ASTR 20

template<int BN>
__device__ __forceinline__ void gemm_core(
    const float* __restrict__ A, const float* __restrict__ Bm,
    float* __restrict__ C, int N, int K, int bm, int bn)
{
    constexpr int BSTR = BN + 8;
    constexpr int NF   = BN / 32;          // n-frags per warp
    constexpr int ASZ  = 128 * ASTR;       // floats per A stage
    constexpr int BSZ  = 16 * BSTR;        // floats per B stage

    extern __shared__ float smg[];
    float* Asm = smg;                      // 3 stages
    float* Bsm = smg + 3 * ASZ;

    const int tid  = threadIdx.x;
    const int lane = tid & 31;
    const int w    = tid >> 5;
    const int wm   = (w >> 2) * 64;        // 0,64
    const int wn   = (w & 3) * (BN / 4);
    const int lr   = lane >> 2;            // 0..7
    const int lc   = lane & 3;             // 0..3

    float acc[4][NF][4];
    #pragma unroll
    for (int mi = 0; mi < 4; mi++)
        #pragma unroll
        for (int nj = 0; nj < NF; nj++)
            #pragma unroll
            for (int u = 0; u < 4; u++) acc[mi][nj][u] = 0.f;

    const int T = K / 16;

    // A: 512 float4 / stage. thread -> rows (tid>>2), (tid>>2)+64, col4 = tid&3.
    const int a_r  = tid >> 2;
    const int a_c4 = (tid & 3) * 4;
    // B: 16*BN/4 float4 / stage.
    constexpr int B4     = 16 * BN / 4;
    constexpr int BPT    = B4 / 256;       // float4 per thread
    constexpr int BROWQ  = BN / 4;         // float4 per row

    auto load_stage = [&](int kt, int buf) {
        float* as = Asm + buf * ASZ;
        const float* ag = A + (size_t)(bm + a_r) * K + kt * 16 + a_c4;
        cp_async16(smem_u32(&as[a_r * ASTR + a_c4]), ag);
        cp_async16(smem_u32(&as[(a_r + 64) * ASTR + a_c4]), ag + (size_t)64 * K);
        float* bs = Bsm + buf * BSZ;
        #pragma unroll
        for (int i = 0; i < BPT; i++) {
            int idx = tid + i * 256;
            int row = idx / BROWQ, c4 = (idx % BROWQ) * 4;
            cp_async16(smem_u32(&bs[row * BSTR + c4]),
                       Bm + (size_t)(kt * 16 + row) * N + bn + c4);
        }
    };

    load_stage(0, 0); CP_COMMIT();
    load_stage(1, 1); CP_COMMIT();

    for (int kt = 0; kt < T; kt++) {
        const int buf = kt % 3;
        asm volatile("cp.async.wait_group 1;" ::: "memory");
        __syncthreads();
        if (kt + 2 < T) load_stage(kt + 2, (kt + 2) % 3);
        CP_COMMIT();

        const float* as = Asm + buf * ASZ;
        const float* bs = Bsm + buf * BSZ;
        #pragma unroll
        for (int ks = 0; ks < 2; ks++) {
            const int kc = lc + ks * 8;
            unsigned af[4][4], bf[NF][2];
            #pragma unroll
            for (int mi = 0; mi < 4; mi++) {
                int r = wm + mi * 16 + lr;
                af[mi][0] = __float_as_uint(as[r * ASTR + kc]);
                af[mi][1] = __float_as_uint(as[(r + 8) * ASTR + kc]);
                af[mi][2] = __float_as_uint(as[r * ASTR + kc + 4]);
                af[mi][3] = __float_as_uint(as[(r + 8) * ASTR + kc + 4]);
            }
            #pragma unroll
            for (int nj = 0; nj < NF; nj++) {
                int cn = wn + nj * 8 + lr;
                bf[nj][0] = __float_as_uint(bs[kc * BSTR + cn]);
                bf[nj][1] = __float_as_uint(bs[(kc + 4) * BSTR + cn]);
            }
            #pragma unroll
            for (int mi = 0; mi < 4; mi++)
                #pragma unroll
                for (int nj = 0; nj < NF; nj++)
                    mma_tf32(acc[mi][nj], af[mi], bf[nj]);
        }
        __syncthreads();
    }

    #pragma unroll
    for (int mi = 0; mi < 4; mi++) {
        int r0 = bm + wm + mi * 16 + lr;
        #pragma unroll
        for (int nj = 0; nj < NF; nj++) {
            int cn = bn + wn + nj * 8 + 2 * lc;
            *(float2*)&C[(size_t)r0 * N + cn] =
                make_float2(acc[mi][nj][0], acc[mi][nj][1]);
            *(float2*)&C[(size_t)(r0 + 8) * N + cn] =
                make_float2(acc[mi][nj][2], acc[mi][nj][3]);
        }
    }
}

__global__ __launch_bounds__(256, 1) void gemm_n256(
    const float* __restrict__ A, const float* __restrict__ Bm,
    float* __restrict__ C)
{
    gemm_core<256>(A, Bm, C, HID_, HID_, blockIdx.y * 128, blockIdx.x * 256);
}

__global__ __launch_bounds__(256, 1) void gemm_kv(
    const float* __restrict__ A,
    const float* __restrict__ Wk, float* __restrict__ Ko,
    const float* __restrict__ Wv, float* __restrict__ Vo)
{
    const int bx = blockIdx.x;
    if (bx < 5)
        gemm_core<128>(A, Wk, Ko, KV_ * D_, HID_, blockIdx.y * 128, bx * 128);
    else
        gemm_core<128>(A, Wv, Vo, KV_ * D_, HID_, blockIdx.y * 128, (bx - 5) * 128);
}

// ---------------------------------------------------------------------------
// RoPE (in-place)
// ---------------------------------------------------------------------------
__global__ void rope_kernel(float* __restrict__ X,
                            const float* __restrict__ cosf,
                            const float* __restrict__ sinf,
                            int nheads, size_t total)
{
    size_t idx = (size_t)blockIdx.x * blockDim.x + threadIdx.x;
    if (idx >= total) return;
    int d = (int)(idx % 40);
    size_t t = idx / 40;
    int head = (int)(t % nheads);
    size_t row = t / nheads;
    int s = (int)(row % S_);

    float* base = X + row * ((size_t)nheads * D_) + (size_t)head * D_;
    float x1 = base[d];
    float x2 = base[d + 40];
    float c1 = cosf[(size_t)s * D_ + d];
    float s1 = sinf[(size_t)s * D_ + d];
    float c2 = cosf[(size_t)s * D_ + d + 40];
    float s2 = sinf[(size_t)s * D_ + d + 40];
    base[d]      = x1 * c1 - x2 * s1;
    base[d + 40] = x2 * c2 + x1 * s2;
}

// ---------------------------------------------------------------------------
// Flash attention via tf32 mma.sync with 3x split-compensation (unchanged)
// ---------------------------------------------------------------------------
#define AQ 84
#define AV 88
#define AP 68

__global__ __launch_bounds__(256) void attn_mma(
    const float* __restrict__ Q, const float* __restrict__ K,
    const float* __restrict__ V, float* __restrict__ O)
{
    extern __shared__ float sm[];
    float* Qhi = sm;
    float* Qlo = Qhi + 64 * AQ;
    float* Khi = Qlo + 64 * AQ;
    float* Klo = Khi + 64 * AQ;
    float* Vhi = Klo + 64 * AQ;
    float* Vlo = Vhi + 64 * AV;
    float* Ph  = Vlo + 64 * AV;
    float* Pl  = Ph  + 64 * AP;
    float* cr  = Pl  + 64 * AP;

    const int tid  = threadIdx.x;
    const int lane = tid & 31;
    const int w    = tid >> 5;
    const int lr   = lane >> 2;
    const int lc   = lane & 3;
    const int wm   = (w >> 1) * 16;
    const int wnq  = (w & 1) * 32;
    const int wnp  = (w & 1) * 40;

    const int bh  = blockIdx.y;
    const int b   = bh / H_;
    const int h   = bh % H_;
    const int kvh = h / G_;
    const int q0  = blockIdx.x * 64;
    const float rscale = 0.11180339887498949f;

    for (int i = tid; i < 64 * 20; i += 256) {
        int r = i / 20, c4 = (i % 20) * 4;
        float4 v = *(const float4*)(Q + ((size_t)(b * S_ + q0 + r)) * (H_ * D_)
                                      + h * D_ + c4);
        v.x *= rscale; v.y *= rscale; v.z *= rscale; v.w *= rscale;
        float4 hi, lo;
        hi.x = tf32_rna(v.x); lo.x = tf32_rna(v.x - hi.x);
        hi.y = tf32_rna(v.y); lo.y = tf32_rna(v.y - hi.y);
        hi.z = tf32_rna(v.z); lo.z = tf32_rna(v.z - hi.z);
        hi.w = tf32_rna(v.w); lo.w = tf32_rna(v.w - hi.w);
        *(float4*)(Qhi + r * AQ + c4) = hi;
        *(float4*)(Qlo + r * AQ + c4) = lo;
    }

    const int myrow = tid >> 2;
    const int myg   = tid & 3;
    float m = -1e30f, l = 0.f;

    float co[5][4];
    #pragma unroll
    for (int nj = 0; nj < 5; nj++)
        #pragma unroll
        for (int u = 0; u < 4; u++) co[nj][u] = 0.f;

    for (int k0 = 0; k0 <= q0; k0 += 64) {
        __syncthreads();
        for (int i = tid; i < 64 * 20; i += 256) {
            int r = i / 20, c4 = (i % 20) * 4;
            size_t base = ((size_t)(b * S_ + k0 + r)) * (KV_ * D_) + kvh * D_ + c4;
            float4 kv = *(const float4*)(K + base);
            float4 vv = *(const float4*)(V + base);
            float4 hi, lo;
            hi.x = tf32_rna(kv.x); lo.x = tf32_rna(kv.x - hi.x);
            hi.y = tf32_rna(kv.y); lo.y = tf32_rna(kv.y - hi.y);
            hi.z = tf32_rna(kv.z); lo.z = tf32_rna(kv.z - hi.z);
            hi.w = tf32_rna(kv.w); lo.w = tf32_rna(kv.w - hi.w);
            *(float4*)(Khi + r * AQ + c4) = hi;
            *(float4*)(Klo + r * AQ + c4) = lo;
            hi.x = tf32_rna(vv.x); lo.x = tf32_rna(vv.x - hi.x);
            hi.y = tf32_rna(vv.y); lo.y = tf32_rna(vv.y - hi.y);
            hi.z = tf32_rna(vv.z); lo.z = tf32_rna(vv.z - hi.z);
            hi.w = tf32_rna(vv.w); lo.w = tf32_rna(vv.w - hi.w);
            *(float4*)(Vhi + r * AV + c4) = hi;
            *(float4*)(Vlo + r * AV + c4) = lo;
        }
        __syncthreads();

        float cq[4][4];
        #pragma unroll
        for (int nj = 0; nj < 4; nj++)
            #pragma unroll
            for (int u = 0; u < 4; u++) cq[nj][u] = 0.f;

        #pragma unroll
        for (int pass = 0; pass < 3; pass++) {
            const float* Av = (pass == 1) ? Qlo : Qhi;
            const float* Bv = (pass == 2) ? Klo : Khi;
            #pragma unroll
            for (int ks = 0; ks < 10; ks++) {
                int kc = ks * 8 + lc;
                unsigned a[4];
                a[0] = __float_as_uint(Av[(wm + lr) * AQ + kc]);
                a[1] = __float_as_uint(Av[(wm + lr + 8) * AQ + kc]);
                a[2] = __float_as_uint(Av[(wm + lr) * AQ + kc + 4]);
                a[3] = __float_as_uint(Av[(wm + lr + 8) * AQ + kc + 4]);
                #pragma unroll
                for (int nj = 0; nj < 4; nj++) {
                    int cn = wnq + nj * 8 + lr;
                    unsigned bb[2];
                    bb[0] = __float_as_uint(Bv[cn * AQ + kc]);
                    bb[1] = __float_as_uint(Bv[cn * AQ + kc + 4]);
                    mma_tf32(cq[nj], a, bb);
                }
            }
        }

        #pragma unroll
        for (int nj = 0; nj < 4; nj++) {
            int col = wnq + nj * 8 + 2 * lc;
            int r0 = wm + lr, r1 = wm + lr + 8;
            Ph[r0 * AP + col]     = (k0 + col     <= q0 + r0) ? cq[nj][0] : -1e30f;
            Ph[r0 * AP + col + 1] = (k0 + col + 1 <= q0 + r0) ? cq[nj][1] : -1e30f;
            Ph[r1 * AP + col]     = (k0 + col     <= q0 + r1) ? cq[nj][2] : -1e30f;
            Ph[r1 * AP + col + 1] = (k0 + col + 1 <= q0 + r1) ? cq[nj][3] : -1e30f;
        }
        __syncthreads();

        float s[16];
        #pragma unroll
        for (int j4 = 0; j4 < 4; j4++) {
            float4 v4 = *(const float4*)(Ph + myrow * AP + myg * 16 + j4 * 4);
            s[j4 * 4 + 0] = v4.x; s[j4 * 4 + 1] = v4.y;
            s[j4 * 4 + 2] = v4.z; s[j4 * 4 + 3] = v4.w;
        }
        float mx = s[0];
        #pragma unroll
        for (int j = 1; j < 16; j++) mx = fmaxf(mx, s[j]);
        mx = fmaxf(mx, __shfl_xor_sync(0xffffffffu, mx, 1));
        mx = fmaxf(mx, __shfl_xor_sync(0xffffffffu, mx, 2));
        float mnew = fmaxf(m, mx);
        float corr = __expf(m - mnew);
        float rs = 0.f;
        #pragma unroll
        for (int j = 0; j < 16; j++) {
            float p = __expf(s[j] - mnew);
            rs += p;
            float phi = tf32_rna(p);
            Ph[myrow * AP + myg * 16 + j] = phi;
            Pl[myrow * AP + myg * 16 + j] = tf32_rna(p - phi);
        }
        rs += __shfl_xor_sync(0xffffffffu, rs, 1);
        rs += __shfl_xor_sync(0xffffffffu, rs, 2);
        m = mnew;
        l = l * corr + rs;
        if (myg == 0) cr[myrow] = corr;
        __syncthreads();

        float c0 = cr[wm + lr], c1 = cr[wm + lr + 8];
        #pragma unroll
        for (int nj = 0; nj < 5; nj++) {
            co[nj][0] *= c0; co[nj][1] *= c0;
            co[nj][2] *= c1; co[nj][3] *= c1;
        }

        #pragma unroll
        for (int pass = 0; pass < 3; pass++) {
            const float* Av = (pass == 1) ? Pl : Ph;
            const float* Bv = (pass == 2) ? Vlo : Vhi;
            #pragma unroll
            for (int ks = 0; ks < 8; ks++) {
                int kc = ks * 8 + lc;
                unsigned a[4];
                a[0] = __float_as_uint(Av[(wm + lr) * AP + kc]);
                a[1] = __float_as_uint(Av[(wm + lr + 8) * AP + kc]);
                a[2] = __float_as_uint(Av[(wm + lr) * AP + kc + 4]);
                a[3] = __float_as_uint(Av[(wm + lr + 8) * AP + kc + 4]);
                #pragma unroll
                for (int nj = 0; nj < 5; nj++) {
                    int cn = wnp + nj * 8 + lr;
                    unsigned bb[2];
                    bb[0] = __float_as_uint(Bv[(kc)     * AV + cn]);
                    bb[1] = __float_as_uint(Bv[(kc + 4) * AV + cn]);
                    mma_tf32(co[nj], a, bb);
                }
            }
        }
    }

    __syncthreads();
    if (myg == 0) cr[myrow] = 1.f / l;
    __syncthreads();
    float i0 = cr[wm + lr], i1 = cr[wm + lr + 8];
    size_t ro0 = ((size_t)(b * S_ + q0 + wm + lr)) * (H_ * D_) + h * D_;
    size_t ro1 = ((size_t)(b * S_ + q0 + wm + lr + 8)) * (H_ * D_) + h * D_;
    #pragma unroll
    for (int nj = 0; nj < 5; nj++) {
        int col = wnp + nj * 8 + 2 * lc;
        *(float2*)(O + ro0 + col) =
            make_float2(tf32_rna(co[nj][0] * i0), tf32_rna(co[nj][1] * i0));
        *(float2*)(O + ro1 + col) =
            make_float2(tf32_rna(co[nj][2] * i1), tf32_rna(co[nj][3] * i1));
    }
}

// ---------------------------------------------------------------------------
// Launch
// ---------------------------------------------------------------------------
extern "C" void kernel_launch(void* const* d_in, const int* in_sizes, int n_in,
                              void* d_out, int out_size)
{
    const float* hs   = (const float*)d_in[0];
    const float* cosf = (const float*)d_in[1];
    const float* sinf = (const float*)d_in[2];
    const float* Wq   = (const float*)d_in[3];
    const float* Wk   = (const float*)d_in[4];
    const float* Wv   = (const float*)d_in[5];
    const float* Wo   = (const float*)d_in[6];
    float* out = (float*)d_out;

    float *Qp, *Kp, *Vp, *Cp, *HSr, *Wqr, *Wkr, *Wvr, *Wor;
    cudaGetSymbolAddress((void**)&Qp,  g_Q);
    cudaGetSymbolAddress((void**)&Kp,  g_K);
    cudaGetSymbolAddress((void**)&Vp,  g_V);
    cudaGetSymbolAddress((void**)&Cp,  g_ctx);
    cudaGetSymbolAddress((void**)&HSr, g_hs_r);
    cudaGetSymbolAddress((void**)&Wqr, g_Wq_r);
    cudaGetSymbolAddress((void**)&Wkr, g_Wk_r);
    cudaGetSymbolAddress((void**)&Wvr, g_Wv_r);
    cudaGetSymbolAddress((void**)&Wor, g_Wo_r);

    // TF32 RNA pre-rounding
    {
        auto rnd = [](const float* src, float* dst, size_t n) {
            int n4 = (int)(n / 4);
            round_tf32<<<(n4 + 255) / 256, 256>>>(
                (const float4*)src, (float4*)dst, n4);
        };
        rnd(hs, HSr, (size_t)BS_ * HID_);
        rnd(Wq, Wqr, (size_t)HID_ * H_ * D_);
        rnd(Wk, Wkr, (size_t)HID_ * KV_ * D_);
        rnd(Wv, Wvr, (size_t)HID_ * KV_ * D_);
        rnd(Wo, Wor, (size_t)H_ * D_ * HID_);
    }

    // GEMM smem sizes
    const int smemQ  = (3 * 128 * ASTR + 3 * 16 * (256 + 8)) * 4;  // 81408
    const int smemKV = (3 * 128 * ASTR + 3 * 16 * (128 + 8)) * 4;  // 56832
    cudaFuncSetAttribute(gemm_n256,
                         cudaFuncAttributeMaxDynamicSharedMemorySize, smemQ);
    cudaFuncSetAttribute(gemm_kv,
                         cudaFuncAttributeMaxDynamicSharedMemorySize, smemKV);

    // Q projection + KV projections
    gemm_n256<<<dim3(HID_ / 256, BS_ / 128), 256, smemQ>>>(HSr, Wqr, Qp);
    gemm_kv<<<dim3(10, BS_ / 128), 256, smemKV>>>(HSr, Wkr, Kp, Wvr, Vp);

    // RoPE
    {
        size_t tq = (size_t)BS_ * H_ * 40;
        size_t tk = (size_t)BS_ * KV_ * 40;
        rope_kernel<<<(unsigned)((tq + 255) / 256), 256>>>(Qp, cosf, sinf, H_, tq);
        rope_kernel<<<(unsigned)((tk + 255) / 256), 256>>>(Kp, cosf, sinf, KV_, tk);
    }

    // Attention
    {
        const int smem = (4 * 64 * AQ + 2 * 64 * AV + 2 * 64 * AP + 64)
                         * (int)sizeof(float);
        cudaFuncSetAttribute(attn_mma,
                             cudaFuncAttributeMaxDynamicSharedMemorySize, smem);
        dim3 ga(S_ / 64, B_ * H_);
        attn_mma<<<ga, 256, smem>>>(Qp, Kp, Vp, Cp);
    }

    // Output projection
    gemm_n256<<<dim3(HID_ / 256, BS_ / 128), 256, smemQ>>>(Cp, Wor, out);
}

// round 6
// speedup vs baseline: 1.1014x; 1.1014x over previous
#include <cuda_runtime.h>
#include <math.h>

// Problem constants
#define B_   2
#define S_   2048
#define HID_ 2560
#define H_   32
#define KV_  8
#define D_   80
#define G_   4
#define BS_  (B_*S_)      // 4096 total rows

// Scratch (device globals)
__device__ float g_Q[(size_t)BS_ * H_ * D_];
__device__ float g_K[(size_t)BS_ * KV_ * D_];
__device__ float g_V[(size_t)BS_ * KV_ * D_];
__device__ float g_ctx[(size_t)BS_ * H_ * D_];
__device__ float g_hs_r[(size_t)BS_ * HID_];
__device__ float g_Wq_r[(size_t)HID_ * H_ * D_];
__device__ float g_Wk_r[(size_t)HID_ * KV_ * D_];
__device__ float g_Wv_r[(size_t)HID_ * KV_ * D_];
__device__ float g_Wo_r[(size_t)H_ * D_ * HID_];

// ---------------------------------------------------------------------------
// Helpers
// ---------------------------------------------------------------------------
__device__ __forceinline__ unsigned smem_u32(const void* p) {
    return (unsigned)__cvta_generic_to_shared(p);
}
__device__ __forceinline__ void cp_async16(unsigned dst, const void* src) {
    asm volatile("cp.async.cg.shared.global [%0], [%1], 16;\n"
                 :: "r"(dst), "l"(src));
}
#define CP_COMMIT() asm volatile("cp.async.commit_group;\n" ::: "memory")
#define CP_WAIT0()  asm volatile("cp.async.wait_group 0;\n" ::: "memory")

__device__ __forceinline__ float tf32_rna(float v) {
    unsigned u;
    asm("cvt.rna.tf32.f32 %0, %1;" : "=r"(u) : "f"(v));
    return __uint_as_float(u);
}

__device__ __forceinline__ void mma_tf32(float* c, const unsigned* a, const unsigned* b) {
    asm volatile(
        "mma.sync.aligned.m16n8k8.row.col.f32.tf32.tf32.f32 "
        "{%0,%1,%2,%3}, {%4,%5,%6,%7}, {%8,%9}, {%0,%1,%2,%3};\n"
        : "+f"(c[0]), "+f"(c[1]), "+f"(c[2]), "+f"(c[3])
        : "r"(a[0]), "r"(a[1]), "r"(a[2]), "r"(a[3]), "r"(b[0]), "r"(b[1]));
}

// ---------------------------------------------------------------------------
// TF32 RNA rounding pre-pass
// ---------------------------------------------------------------------------
__global__ void round_tf32(const float4* __restrict__ in,
                           float4* __restrict__ out, int n4)
{
    int i = blockIdx.x * blockDim.x + threadIdx.x;
    if (i < n4) {
        float4 v = in[i];
        v.x = tf32_rna(v.x); v.y = tf32_rna(v.y);
        v.z = tf32_rna(v.z); v.w = tf32_rna(v.w);
        out[i] = v;
    }
}

// ---------------------------------------------------------------------------
// TF32 tensor-core GEMM (round-2 proven config, untouched)
// ---------------------------------------------------------------------------
#define ASTR 20
#define BSTR 136

__device__ __forceinline__ void gemm_core(
    const float* __restrict__ A, const float* __restrict__ Bm,
    float* __restrict__ C, int N, int K, int bm, int bn)
{
    __shared__ float As[2][128 * ASTR];
    __shared__ float Bs[2][16 * BSTR];

    const int tid  = threadIdx.x;
    const int lane = tid & 31;
    const int w    = tid >> 5;
    const int wm   = (w >> 2) * 64;
    const int wn   = (w & 3) * 32;
    const int lr   = lane >> 2;
    const int lc   = lane & 3;

    const int a_row = tid >> 2;
    const int a_col = (tid & 3) * 4;
    const int b_row = tid >> 5;
    const int b_col = (tid & 31) * 4;

    float acc[4][4][4];
    #pragma unroll
    for (int mi = 0; mi < 4; mi++)
        #pragma unroll
        for (int nj = 0; nj < 4; nj++)
            #pragma unroll
            for (int u = 0; u < 4; u++) acc[mi][nj][u] = 0.f;

    const int T = K / 16;

    auto load_tile = [&](int kt, int buf) {
        const float* ag = A + (size_t)(bm + a_row) * K + kt * 16 + a_col;
        unsigned as0 = smem_u32(&As[buf][a_row * ASTR + a_col]);
        cp_async16(as0, ag);
        cp_async16(as0 + 64 * ASTR * 4, ag + (size_t)64 * K);
        const float* bg = Bm + (size_t)(kt * 16 + b_row) * N + bn + b_col;
        unsigned bs0 = smem_u32(&Bs[buf][b_row * BSTR + b_col]);
        cp_async16(bs0, bg);
        cp_async16(bs0 + 8 * BSTR * 4, bg + (size_t)8 * N);
    };

    load_tile(0, 0);
    CP_COMMIT();

    for (int kt = 0; kt < T; kt++) {
        const int buf = kt & 1;
        CP_WAIT0();
        __syncthreads();
        if (kt + 1 < T) {
            load_tile(kt + 1, buf ^ 1);
            CP_COMMIT();
        }
        #pragma unroll
        for (int ks = 0; ks < 2; ks++) {
            const int kc = lc + ks * 8;
            unsigned af[4][4], bf[4][2];
            #pragma unroll
            for (int mi = 0; mi < 4; mi++) {
                int r = wm + mi * 16 + lr;
                af[mi][0] = __float_as_uint(As[buf][r * ASTR + kc]);
                af[mi][1] = __float_as_uint(As[buf][(r + 8) * ASTR + kc]);
                af[mi][2] = __float_as_uint(As[buf][r * ASTR + kc + 4]);
                af[mi][3] = __float_as_uint(As[buf][(r + 8) * ASTR + kc + 4]);
            }
            #pragma unroll
            for (int nj = 0; nj < 4; nj++) {
                int cn = wn + nj * 8 + lr;
                bf[nj][0] = __float_as_uint(Bs[buf][kc * BSTR + cn]);
                bf[nj][1] = __float_as_uint(Bs[buf][(kc + 4) * BSTR + cn]);
            }
            #pragma unroll
            for (int mi = 0; mi < 4; mi++)
                #pragma unroll
                for (int nj = 0; nj < 4; nj++)
                    mma_tf32(acc[mi][nj], af[mi], bf[nj]);
        }
        __syncthreads();
    }

    #pragma unroll
    for (int mi = 0; mi < 4; mi++) {
        int r0 = bm + wm + mi * 16 + lr;
        #pragma unroll
        for (int nj = 0; nj < 4; nj++) {
            int cn = bn + wn + nj * 8 + 2 * lc;
            *(float2*)&C[(size_t)r0 * N + cn] =
                make_float2(acc[mi][nj][0], acc[mi][nj][1]);
            *(float2*)&C[(size_t)(r0 + 8) * N + cn] =
                make_float2(acc[mi][nj][2], acc[mi][nj][3]);
        }
    }
}

__global__ __launch_bounds__(256, 2) void gemm_tf32(
    const float* __restrict__ A, const float* __restrict__ Bm,
    float* __restrict__ C, int N, int K)
{
    gemm_core(A, Bm, C, N, K, blockIdx.y * 128, blockIdx.x * 128);
}

__global__ __launch_bounds__(256, 2) void gemm_qkv(
    const float* __restrict__ A,
    const float* __restrict__ Wq, float* __restrict__ Qo,
    const float* __restrict__ Wk, float* __restrict__ Ko,
    const float* __restrict__ Wv, float* __restrict__ Vo)
{
    const int bx = blockIdx.x;
    const int bm = blockIdx.y * 128;
    if (bx < 20)       gemm_core(A, Wq, Qo, HID_,      HID_, bm, bx * 128);
    else if (bx < 25)  gemm_core(A, Wk, Ko, KV_ * D_,  HID_, bm, (bx - 20) * 128);
    else               gemm_core(A, Wv, Vo, KV_ * D_,  HID_, bm, (bx - 25) * 128);
}

// ---------------------------------------------------------------------------
// RoPE (in-place)
// ---------------------------------------------------------------------------
__global__ void rope_kernel(float* __restrict__ X,
                            const float* __restrict__ cosf,
                            const float* __restrict__ sinf,
                            int nheads, size_t total)
{
    size_t idx = (size_t)blockIdx.x * blockDim.x + threadIdx.x;
    if (idx >= total) return;
    int d = (int)(idx % 40);
    size_t t = idx / 40;
    int head = (int)(t % nheads);
    size_t row = t / nheads;
    int s = (int)(row % S_);

    float* base = X + row * ((size_t)nheads * D_) + (size_t)head * D_;
    float x1 = base[d];
    float x2 = base[d + 40];
    float c1 = cosf[(size_t)s * D_ + d];
    float s1 = sinf[(size_t)s * D_ + d];
    float c2 = cosf[(size_t)s * D_ + d + 40];
    float s2 = sinf[(size_t)s * D_ + d + 40];
    base[d]      = x1 * c1 - x2 * s1;
    base[d + 40] = x2 * c2 + x1 * s2;
}

// ---------------------------------------------------------------------------
// Flash attention via tf32 mma with compensation.
// QK: 3-term (Qhi·Khi + Qlo·Khi + Qhi·Klo), fragments loaded once per k-step.
// PV: 2-term (Phi·Vhi + Phi·Vlo) — Pl·V term dropped (~2^-12 rel on ctx).
// ---------------------------------------------------------------------------
#define AQ 84
#define AV 88
#define AP 68

__global__ __launch_bounds__(256) void attn_mma(
    const float* __restrict__ Q, const float* __restrict__ K,
    const float* __restrict__ V, float* __restrict__ O)
{
    extern __shared__ float sm[];
    float* Qhi = sm;
    float* Qlo = Qhi + 64 * AQ;
    float* Khi = Qlo + 64 * AQ;
    float* Klo = Khi + 64 * AQ;
    float* Vhi = Klo + 64 * AQ;
    float* Vlo = Vhi + 64 * AV;
    float* Ph  = Vlo + 64 * AV;
    float* cr  = Ph  + 64 * AP;

    const int tid  = threadIdx.x;
    const int lane = tid & 31;
    const int w    = tid >> 5;
    const int lr   = lane >> 2;
    const int lc   = lane & 3;
    const int wm   = (w >> 1) * 16;
    const int wnq  = (w & 1) * 32;
    const int wnp  = (w & 1) * 40;

    const int bh  = blockIdx.y;
    const int b   = bh / H_;
    const int h   = bh % H_;
    const int kvh = h / G_;
    const int q0  = blockIdx.x * 64;
    const float rscale = 0.11180339887498949f;

    for (int i = tid; i < 64 * 20; i += 256) {
        int r = i / 20, c4 = (i % 20) * 4;
        float4 v = *(const float4*)(Q + ((size_t)(b * S_ + q0 + r)) * (H_ * D_)
                                      + h * D_ + c4);
        v.x *= rscale; v.y *= rscale; v.z *= rscale; v.w *= rscale;
        float4 hi, lo;
        hi.x = tf32_rna(v.x); lo.x = tf32_rna(v.x - hi.x);
        hi.y = tf32_rna(v.y); lo.y = tf32_rna(v.y - hi.y);
        hi.z = tf32_rna(v.z); lo.z = tf32_rna(v.z - hi.z);
        hi.w = tf32_rna(v.w); lo.w = tf32_rna(v.w - hi.w);
        *(float4*)(Qhi + r * AQ + c4) = hi;
        *(float4*)(Qlo + r * AQ + c4) = lo;
    }

    const int myrow = tid >> 2;
    const int myg   = tid & 3;
    float m = -1e30f, l = 0.f;

    float co[5][4];
    #pragma unroll
    for (int nj = 0; nj < 5; nj++)
        #pragma unroll
        for (int u = 0; u < 4; u++) co[nj][u] = 0.f;

    for (int k0 = 0; k0 <= q0; k0 += 64) {
        __syncthreads();
        for (int i = tid; i < 64 * 20; i += 256) {
            int r = i / 20, c4 = (i % 20) * 4;
            size_t base = ((size_t)(b * S_ + k0 + r)) * (KV_ * D_) + kvh * D_ + c4;
            float4 kv = *(const float4*)(K + base);
            float4 vv = *(const float4*)(V + base);
            float4 hi, lo;
            hi.x = tf32_rna(kv.x); lo.x = tf32_rna(kv.x - hi.x);
            hi.y = tf32_rna(kv.y); lo.y = tf32_rna(kv.y - hi.y);
            hi.z = tf32_rna(kv.z); lo.z = tf32_rna(kv.z - hi.z);
            hi.w = tf32_rna(kv.w); lo.w = tf32_rna(kv.w - hi.w);
            *(float4*)(Khi + r * AQ + c4) = hi;
            *(float4*)(Klo + r * AQ + c4) = lo;
            hi.x = tf32_rna(vv.x); lo.x = tf32_rna(vv.x - hi.x);
            hi.y = tf32_rna(vv.y); lo.y = tf32_rna(vv.y - hi.y);
            hi.z = tf32_rna(vv.z); lo.z = tf32_rna(vv.z - hi.z);
            hi.w = tf32_rna(vv.w); lo.w = tf32_rna(vv.w - hi.w);
            *(float4*)(Vhi + r * AV + c4) = hi;
            *(float4*)(Vlo + r * AV + c4) = lo;
        }
        __syncthreads();

        // QK^T: 3-term compensation, shared fragment loads
        float cq[4][4];
        #pragma unroll
        for (int nj = 0; nj < 4; nj++)
            #pragma unroll
            for (int u = 0; u < 4; u++) cq[nj][u] = 0.f;

        #pragma unroll
        for (int ks = 0; ks < 10; ks++) {
            const int kc = ks * 8 + lc;
            unsigned ah[4], al[4];
            ah[0] = __float_as_uint(Qhi[(wm + lr) * AQ + kc]);
            ah[1] = __float_as_uint(Qhi[(wm + lr + 8) * AQ + kc]);
            ah[2] = __float_as_uint(Qhi[(wm + lr) * AQ + kc + 4]);
            ah[3] = __float_as_uint(Qhi[(wm + lr + 8) * AQ + kc + 4]);
            al[0] = __float_as_uint(Qlo[(wm + lr) * AQ + kc]);
            al[1] = __float_as_uint(Qlo[(wm + lr + 8) * AQ + kc]);
            al[2] = __float_as_uint(Qlo[(wm + lr) * AQ + kc + 4]);
            al[3] = __float_as_uint(Qlo[(wm + lr + 8) * AQ + kc + 4]);
            #pragma unroll
            for (int nj = 0; nj < 4; nj++) {
                int cn = wnq + nj * 8 + lr;
                unsigned bh_[2], bl_[2];
                bh_[0] = __float_as_uint(Khi[cn * AQ + kc]);
                bh_[1] = __float_as_uint(Khi[cn * AQ + kc + 4]);
                bl_[0] = __float_as_uint(Klo[cn * AQ + kc]);
                bl_[1] = __float_as_uint(Klo[cn * AQ + kc + 4]);
                mma_tf32(cq[nj], ah, bh_);
                mma_tf32(cq[nj], al, bh_);
                mma_tf32(cq[nj], ah, bl_);
            }
        }

        // Mask + store raw scores
        #pragma unroll
        for (int nj = 0; nj < 4; nj++) {
            int col = wnq + nj * 8 + 2 * lc;
            int r0 = wm + lr, r1 = wm + lr + 8;
            Ph[r0 * AP + col]     = (k0 + col     <= q0 + r0) ? cq[nj][0] : -1e30f;
            Ph[r0 * AP + col + 1] = (k0 + col + 1 <= q0 + r0) ? cq[nj][1] : -1e30f;
            Ph[r1 * AP + col]     = (k0 + col     <= q0 + r1) ? cq[nj][2] : -1e30f;
            Ph[r1 * AP + col + 1] = (k0 + col + 1 <= q0 + r1) ? cq[nj][3] : -1e30f;
        }
        __syncthreads();

        // Online softmax
        float s[16];
        #pragma unroll
        for (int j4 = 0; j4 < 4; j4++) {
            float4 v4 = *(const float4*)(Ph + myrow * AP + myg * 16 + j4 * 4);
            s[j4 * 4 + 0] = v4.x; s[j4 * 4 + 1] = v4.y;
            s[j4 * 4 + 2] = v4.z; s[j4 * 4 + 3] = v4.w;
        }
        float mx = s[0];
        #pragma unroll
        for (int j = 1; j < 16; j++) mx = fmaxf(mx, s[j]);
        mx = fmaxf(mx, __shfl_xor_sync(0xffffffffu, mx, 1));
        mx = fmaxf(mx, __shfl_xor_sync(0xffffffffu, mx, 2));
        float mnew = fmaxf(m, mx);
        float corr = __expf(m - mnew);
        float rs = 0.f;
        #pragma unroll
        for (int j = 0; j < 16; j++) {
            float p = __expf(s[j] - mnew);
            rs += p;
            Ph[myrow * AP + myg * 16 + j] = tf32_rna(p);
        }
        rs += __shfl_xor_sync(0xffffffffu, rs, 1);
        rs += __shfl_xor_sync(0xffffffffu, rs, 2);
        m = mnew;
        l = l * corr + rs;
        if (myg == 0) cr[myrow] = corr;
        __syncthreads();

        // Rescale O frags
        float c0 = cr[wm + lr], c1 = cr[wm + lr + 8];
        #pragma unroll
        for (int nj = 0; nj < 5; nj++) {
            co[nj][0] *= c0; co[nj][1] *= c0;
            co[nj][2] *= c1; co[nj][3] *= c1;
        }

        // P@V: 2-term (Phi·Vhi + Phi·Vlo), shared fragment loads
        #pragma unroll
        for (int ks = 0; ks < 8; ks++) {
            const int kc = ks * 8 + lc;
            unsigned a[4];
            a[0] = __float_as_uint(Ph[(wm + lr) * AP + kc]);
            a[1] = __float_as_uint(Ph[(wm + lr + 8) * AP + kc]);
            a[2] = __float_as_uint(Ph[(wm + lr) * AP + kc + 4]);
            a[3] = __float_as_uint(Ph[(wm + lr + 8) * AP + kc + 4]);
            #pragma unroll
            for (int nj = 0; nj < 5; nj++) {
                int cn = wnp + nj * 8 + lr;
                unsigned bh_[2], bl_[2];
                bh_[0] = __float_as_uint(Vhi[(kc)     * AV + cn]);
                bh_[1] = __float_as_uint(Vhi[(kc + 4) * AV + cn]);
                bl_[0] = __float_as_uint(Vlo[(kc)     * AV + cn]);
                bl_[1] = __float_as_uint(Vlo[(kc + 4) * AV + cn]);
                mma_tf32(co[nj], a, bh_);
                mma_tf32(co[nj], a, bl_);
            }
        }
    }

    // Epilogue
    __syncthreads();
    if (myg == 0) cr[myrow] = 1.f / l;
    __syncthreads();
    float i0 = cr[wm + lr], i1 = cr[wm + lr + 8];
    size_t ro0 = ((size_t)(b * S_ + q0 + wm + lr)) * (H_ * D_) + h * D_;
    size_t ro1 = ((size_t)(b * S_ + q0 + wm + lr + 8)) * (H_ * D_) + h * D_;
    #pragma unroll
    for (int nj = 0; nj < 5; nj++) {
        int col = wnp + nj * 8 + 2 * lc;
        *(float2*)(O + ro0 + col) =
            make_float2(tf32_rna(co[nj][0] * i0), tf32_rna(co[nj][1] * i0));
        *(float2*)(O + ro1 + col) =
            make_float2(tf32_rna(co[nj][2] * i1), tf32_rna(co[nj][3] * i1));
    }
}

// ---------------------------------------------------------------------------
// Launch
// ---------------------------------------------------------------------------
extern "C" void kernel_launch(void* const* d_in, const int* in_sizes, int n_in,
                              void* d_out, int out_size)
{
    const float* hs   = (const float*)d_in[0];
    const float* cosf = (const float*)d_in[1];
    const float* sinf = (const float*)d_in[2];
    const float* Wq   = (const float*)d_in[3];
    const float* Wk   = (const float*)d_in[4];
    const float* Wv   = (const float*)d_in[5];
    const float* Wo   = (const float*)d_in[6];
    float* out = (float*)d_out;

    float *Qp, *Kp, *Vp, *Cp, *HSr, *Wqr, *Wkr, *Wvr, *Wor;
    cudaGetSymbolAddress((void**)&Qp,  g_Q);
    cudaGetSymbolAddress((void**)&Kp,  g_K);
    cudaGetSymbolAddress((void**)&Vp,  g_V);
    cudaGetSymbolAddress((void**)&Cp,  g_ctx);
    cudaGetSymbolAddress((void**)&HSr, g_hs_r);
    cudaGetSymbolAddress((void**)&Wqr, g_Wq_r);
    cudaGetSymbolAddress((void**)&Wkr, g_Wk_r);
    cudaGetSymbolAddress((void**)&Wvr, g_Wv_r);
    cudaGetSymbolAddress((void**)&Wor, g_Wo_r);

    // TF32 RNA pre-rounding
    {
        auto rnd = [](const float* src, float* dst, size_t n) {
            int n4 = (int)(n / 4);
            round_tf32<<<(n4 + 255) / 256, 256>>>(
                (const float4*)src, (float4*)dst, n4);
        };
        rnd(hs, HSr, (size_t)BS_ * HID_);
        rnd(Wq, Wqr, (size_t)HID_ * H_ * D_);
        rnd(Wk, Wkr, (size_t)HID_ * KV_ * D_);
        rnd(Wv, Wvr, (size_t)HID_ * KV_ * D_);
        rnd(Wo, Wor, (size_t)H_ * D_ * HID_);
    }

    // Fused QKV projection
    {
        dim3 g(30, BS_ / 128);
        gemm_qkv<<<g, 256>>>(HSr, Wqr, Qp, Wkr, Kp, Wvr, Vp);
    }

    // RoPE on Q and K
    {
        size_t tq = (size_t)BS_ * H_ * 40;
        size_t tk = (size_t)BS_ * KV_ * 40;
        rope_kernel<<<(unsigned)((tq + 255) / 256), 256>>>(Qp, cosf, sinf, H_, tq);
        rope_kernel<<<(unsigned)((tk + 255) / 256), 256>>>(Kp, cosf, sinf, KV_, tk);
    }

    // Attention (tensor-core, compensated)
    {
        const int smem = (4 * 64 * AQ + 2 * 64 * AV + 64 * AP + 64)
                         * (int)sizeof(float);   // 148,736 B
        cudaFuncSetAttribute(attn_mma,
                             cudaFuncAttributeMaxDynamicSharedMemorySize, smem);
        dim3 ga(S_ / 64, B_ * H_);
        attn_mma<<<ga, 256, smem>>>(Qp, Kp, Vp, Cp);
    }

    // Output projection
    {
        dim3 go(HID_ / 128, BS_ / 128);
        gemm_tf32<<<go, 256>>>(Cp, Wor, out, HID_, HID_);
    }
}

// round 7
// speedup vs baseline: 1.2758x; 1.1583x over previous
#include <cuda_runtime.h>
#include <math.h>

// Problem constants
#define B_   2
#define S_   2048
#define HID_ 2560
#define H_   32
#define KV_  8
#define D_   80
#define G_   4
#define BS_  (B_*S_)      // 4096 total rows

// Scratch (device globals)
__device__ float g_Q[(size_t)BS_ * H_ * D_];
__device__ float g_K[(size_t)BS_ * KV_ * D_];
__device__ float g_V[(size_t)BS_ * KV_ * D_];
__device__ float g_ctx[(size_t)BS_ * H_ * D_];
__device__ float g_hs_r[(size_t)BS_ * HID_];
__device__ float g_Wq_r[(size_t)HID_ * H_ * D_];
__device__ float g_Wk_r[(size_t)HID_ * KV_ * D_];
__device__ float g_Wv_r[(size_t)HID_ * KV_ * D_];
__device__ float g_Wo_r[(size_t)H_ * D_ * HID_];

// ---------------------------------------------------------------------------
// Helpers
// ---------------------------------------------------------------------------
__device__ __forceinline__ unsigned smem_u32(const void* p) {
    return (unsigned)__cvta_generic_to_shared(p);
}
__device__ __forceinline__ void cp_async16(unsigned dst, const void* src) {
    asm volatile("cp.async.cg.shared.global [%0], [%1], 16;\n"
                 :: "r"(dst), "l"(src));
}
#define CP_COMMIT() asm volatile("cp.async.commit_group;\n" ::: "memory")
#define CP_WAIT0()  asm volatile("cp.async.wait_group 0;\n" ::: "memory")

__device__ __forceinline__ float tf32_rna(float v) {
    unsigned u;
    asm("cvt.rna.tf32.f32 %0, %1;" : "=r"(u) : "f"(v));
    return __uint_as_float(u);
}

__device__ __forceinline__ void mma_tf32(float* c, const unsigned* a, const unsigned* b) {
    asm volatile(
        "mma.sync.aligned.m16n8k8.row.col.f32.tf32.tf32.f32 "
        "{%0,%1,%2,%3}, {%4,%5,%6,%7}, {%8,%9}, {%0,%1,%2,%3};\n"
        : "+f"(c[0]), "+f"(c[1]), "+f"(c[2]), "+f"(c[3])
        : "r"(a[0]), "r"(a[1]), "r"(a[2]), "r"(a[3]), "r"(b[0]), "r"(b[1]));
}

// ---------------------------------------------------------------------------
// TF32 RNA rounding pre-pass
// ---------------------------------------------------------------------------
__global__ void round_tf32(const float4* __restrict__ in,
                           float4* __restrict__ out, int n4)
{
    int i = blockIdx.x * blockDim.x + threadIdx.x;
    if (i < n4) {
        float4 v = in[i];
        v.x = tf32_rna(v.x); v.y = tf32_rna(v.y);
        v.z = tf32_rna(v.z); v.w = tf32_rna(v.w);
        out[i] = v;
    }
}

// ---------------------------------------------------------------------------
// TF32 tensor-core GEMM (round-2 proven config, untouched)
// ---------------------------------------------------------------------------
#define ASTR 20
#define BSTR 136

__device__ __forceinline__ void gemm_core(
    const float* __restrict__ A, const float* __restrict__ Bm,
    float* __restrict__ C, int N, int K, int bm, int bn)
{
    __shared__ float As[2][128 * ASTR];
    __shared__ float Bs[2][16 * BSTR];

    const int tid  = threadIdx.x;
    const int lane = tid & 31;
    const int w    = tid >> 5;
    const int wm   = (w >> 2) * 64;
    const int wn   = (w & 3) * 32;
    const int lr   = lane >> 2;
    const int lc   = lane & 3;

    const int a_row = tid >> 2;
    const int a_col = (tid & 3) * 4;
    const int b_row = tid >> 5;
    const int b_col = (tid & 31) * 4;

    float acc[4][4][4];
    #pragma unroll
    for (int mi = 0; mi < 4; mi++)
        #pragma unroll
        for (int nj = 0; nj < 4; nj++)
            #pragma unroll
            for (int u = 0; u < 4; u++) acc[mi][nj][u] = 0.f;

    const int T = K / 16;

    auto load_tile = [&](int kt, int buf) {
        const float* ag = A + (size_t)(bm + a_row) * K + kt * 16 + a_col;
        unsigned as0 = smem_u32(&As[buf][a_row * ASTR + a_col]);
        cp_async16(as0, ag);
        cp_async16(as0 + 64 * ASTR * 4, ag + (size_t)64 * K);
        const float* bg = Bm + (size_t)(kt * 16 + b_row) * N + bn + b_col;
        unsigned bs0 = smem_u32(&Bs[buf][b_row * BSTR + b_col]);
        cp_async16(bs0, bg);
        cp_async16(bs0 + 8 * BSTR * 4, bg + (size_t)8 * N);
    };

    load_tile(0, 0);
    CP_COMMIT();

    for (int kt = 0; kt < T; kt++) {
        const int buf = kt & 1;
        CP_WAIT0();
        __syncthreads();
        if (kt + 1 < T) {
            load_tile(kt + 1, buf ^ 1);
            CP_COMMIT();
        }
        #pragma unroll
        for (int ks = 0; ks < 2; ks++) {
            const int kc = lc + ks * 8;
            unsigned af[4][4], bf[4][2];
            #pragma unroll
            for (int mi = 0; mi < 4; mi++) {
                int r = wm + mi * 16 + lr;
                af[mi][0] = __float_as_uint(As[buf][r * ASTR + kc]);
                af[mi][1] = __float_as_uint(As[buf][(r + 8) * ASTR + kc]);
                af[mi][2] = __float_as_uint(As[buf][r * ASTR + kc + 4]);
                af[mi][3] = __float_as_uint(As[buf][(r + 8) * ASTR + kc + 4]);
            }
            #pragma unroll
            for (int nj = 0; nj < 4; nj++) {
                int cn = wn + nj * 8 + lr;
                bf[nj][0] = __float_as_uint(Bs[buf][kc * BSTR + cn]);
                bf[nj][1] = __float_as_uint(Bs[buf][(kc + 4) * BSTR + cn]);
            }
            #pragma unroll
            for (int mi = 0; mi < 4; mi++)
                #pragma unroll
                for (int nj = 0; nj < 4; nj++)
                    mma_tf32(acc[mi][nj], af[mi], bf[nj]);
        }
        __syncthreads();
    }

    #pragma unroll
    for (int mi = 0; mi < 4; mi++) {
        int r0 = bm + wm + mi * 16 + lr;
        #pragma unroll
        for (int nj = 0; nj < 4; nj++) {
            int cn = bn + wn + nj * 8 + 2 * lc;
            *(float2*)&C[(size_t)r0 * N + cn] =
                make_float2(acc[mi][nj][0], acc[mi][nj][1]);
            *(float2*)&C[(size_t)(r0 + 8) * N + cn] =
                make_float2(acc[mi][nj][2], acc[mi][nj][3]);
        }
    }
}

__global__ __launch_bounds__(256, 2) void gemm_tf32(
    const float* __restrict__ A, const float* __restrict__ Bm,
    float* __restrict__ C, int N, int K)
{
    gemm_core(A, Bm, C, N, K, blockIdx.y * 128, blockIdx.x * 128);
}

__global__ __launch_bounds__(256, 2) void gemm_qkv(
    const float* __restrict__ A,
    const float* __restrict__ Wq, float* __restrict__ Qo,
    const float* __restrict__ Wk, float* __restrict__ Ko,
    const float* __restrict__ Wv, float* __restrict__ Vo)
{
    const int bx = blockIdx.x;
    const int bm = blockIdx.y * 128;
    if (bx < 20)       gemm_core(A, Wq, Qo, HID_,      HID_, bm, bx * 128);
    else if (bx < 25)  gemm_core(A, Wk, Ko, KV_ * D_,  HID_, bm, (bx - 20) * 128);
    else               gemm_core(A, Wv, Vo, KV_ * D_,  HID_, bm, (bx - 25) * 128);
}

// ---------------------------------------------------------------------------
// RoPE (in-place)
// ---------------------------------------------------------------------------
__global__ void rope_kernel(float* __restrict__ X,
                            const float* __restrict__ cosf,
                            const float* __restrict__ sinf,
                            int nheads, size_t total)
{
    size_t idx = (size_t)blockIdx.x * blockDim.x + threadIdx.x;
    if (idx >= total) return;
    int d = (int)(idx % 40);
    size_t t = idx / 40;
    int head = (int)(t % nheads);
    size_t row = t / nheads;
    int s = (int)(row % S_);

    float* base = X + row * ((size_t)nheads * D_) + (size_t)head * D_;
    float x1 = base[d];
    float x2 = base[d + 40];
    float c1 = cosf[(size_t)s * D_ + d];
    float s1 = sinf[(size_t)s * D_ + d];
    float c2 = cosf[(size_t)s * D_ + d + 40];
    float s2 = sinf[(size_t)s * D_ + d + 40];
    base[d]      = x1 * c1 - x2 * s1;
    base[d + 40] = x2 * c2 + x1 * s2;
}

// ---------------------------------------------------------------------------
// Flash attention, 2 query heads per block (GQA K/V sharing).
// Same compensated arithmetic as round 6:
//   QK: Qhi·Khi + Qlo·Khi + Qhi·Klo ;  PV: Phi·Vhi + Phi·Vlo.
// Two Ph buffers keep barrier count at 4/ktile while covering 2 heads.
// ---------------------------------------------------------------------------
#define AQ 84
#define AV 88
#define AP 68

__global__ __launch_bounds__(256, 1) void attn_mma2(
    const float* __restrict__ Q, const float* __restrict__ K,
    const float* __restrict__ V, float* __restrict__ O)
{
    extern __shared__ float sm[];
    float* Qhi0 = sm;                    // 64*AQ each
    float* Qlo0 = Qhi0 + 64 * AQ;
    float* Qhi1 = Qlo0 + 64 * AQ;
    float* Qlo1 = Qhi1 + 64 * AQ;
    float* Khi  = Qlo1 + 64 * AQ;
    float* Klo  = Khi  + 64 * AQ;
    float* Vhi  = Klo  + 64 * AQ;        // 64*AV each
    float* Vlo  = Vhi  + 64 * AV;
    float* Ph0  = Vlo  + 64 * AV;        // 64*AP each
    float* Ph1  = Ph0  + 64 * AP;
    float* cr0  = Ph1  + 64 * AP;        // 64 each
    float* cr1  = cr0  + 64;

    const int tid  = threadIdx.x;
    const int lane = tid & 31;
    const int w    = tid >> 5;
    const int lr   = lane >> 2;
    const int lc   = lane & 3;
    const int wm   = (w >> 1) * 16;
    const int wnq  = (w & 1) * 32;
    const int wnp  = (w & 1) * 40;

    const int by  = blockIdx.y;          // 0..31
    const int b   = by >> 4;
    const int kvh = (by >> 1) & 7;
    const int hp  = by & 1;
    const int h0  = kvh * G_ + hp * 2;   // heads h0, h0+1
    const int q0  = blockIdx.x * 64;
    const float rscale = 0.11180339887498949f;

    // Load + scale + split Q for both heads
    #pragma unroll
    for (int hh = 0; hh < 2; hh++) {
        float* qh = hh ? Qhi1 : Qhi0;
        float* ql = hh ? Qlo1 : Qlo0;
        for (int i = tid; i < 64 * 20; i += 256) {
            int r = i / 20, c4 = (i % 20) * 4;
            float4 v = *(const float4*)(Q + ((size_t)(b * S_ + q0 + r)) * (H_ * D_)
                                          + (h0 + hh) * D_ + c4);
            v.x *= rscale; v.y *= rscale; v.z *= rscale; v.w *= rscale;
            float4 hi, lo;
            hi.x = tf32_rna(v.x); lo.x = tf32_rna(v.x - hi.x);
            hi.y = tf32_rna(v.y); lo.y = tf32_rna(v.y - hi.y);
            hi.z = tf32_rna(v.z); lo.z = tf32_rna(v.z - hi.z);
            hi.w = tf32_rna(v.w); lo.w = tf32_rna(v.w - hi.w);
            *(float4*)(qh + r * AQ + c4) = hi;
            *(float4*)(ql + r * AQ + c4) = lo;
        }
    }

    const int myrow = tid >> 2;
    const int myg   = tid & 3;
    float mm[2] = {-1e30f, -1e30f};
    float ll[2] = {0.f, 0.f};

    float co[2][5][4];
    #pragma unroll
    for (int hh = 0; hh < 2; hh++)
        #pragma unroll
        for (int nj = 0; nj < 5; nj++)
            #pragma unroll
            for (int u = 0; u < 4; u++) co[hh][nj][u] = 0.f;

    for (int k0 = 0; k0 <= q0; k0 += 64) {
        __syncthreads();   // prev PV/Ph reads done (first iter: Q writes visible)
        for (int i = tid; i < 64 * 20; i += 256) {
            int r = i / 20, c4 = (i % 20) * 4;
            size_t base = ((size_t)(b * S_ + k0 + r)) * (KV_ * D_) + kvh * D_ + c4;
            float4 kv = *(const float4*)(K + base);
            float4 vv = *(const float4*)(V + base);
            float4 hi, lo;
            hi.x = tf32_rna(kv.x); lo.x = tf32_rna(kv.x - hi.x);
            hi.y = tf32_rna(kv.y); lo.y = tf32_rna(kv.y - hi.y);
            hi.z = tf32_rna(kv.z); lo.z = tf32_rna(kv.z - hi.z);
            hi.w = tf32_rna(kv.w); lo.w = tf32_rna(kv.w - hi.w);
            *(float4*)(Khi + r * AQ + c4) = hi;
            *(float4*)(Klo + r * AQ + c4) = lo;
            hi.x = tf32_rna(vv.x); lo.x = tf32_rna(vv.x - hi.x);
            hi.y = tf32_rna(vv.y); lo.y = tf32_rna(vv.y - hi.y);
            hi.z = tf32_rna(vv.z); lo.z = tf32_rna(vv.z - hi.z);
            hi.w = tf32_rna(vv.w); lo.w = tf32_rna(vv.w - hi.w);
            *(float4*)(Vhi + r * AV + c4) = hi;
            *(float4*)(Vlo + r * AV + c4) = lo;
        }
        __syncthreads();

        // QK^T for both heads
        #pragma unroll
        for (int hh = 0; hh < 2; hh++) {
            const float* Qh = hh ? Qhi1 : Qhi0;
            const float* Ql = hh ? Qlo1 : Qlo0;
            float* Ps = hh ? Ph1 : Ph0;

            float cq[4][4];
            #pragma unroll
            for (int nj = 0; nj < 4; nj++)
                #pragma unroll
                for (int u = 0; u < 4; u++) cq[nj][u] = 0.f;

            #pragma unroll
            for (int ks = 0; ks < 10; ks++) {
                const int kc = ks * 8 + lc;
                unsigned ah[4], al[4];
                ah[0] = __float_as_uint(Qh[(wm + lr) * AQ + kc]);
                ah[1] = __float_as_uint(Qh[(wm + lr + 8) * AQ + kc]);
                ah[2] = __float_as_uint(Qh[(wm + lr) * AQ + kc + 4]);
                ah[3] = __float_as_uint(Qh[(wm + lr + 8) * AQ + kc + 4]);
                al[0] = __float_as_uint(Ql[(wm + lr) * AQ + kc]);
                al[1] = __float_as_uint(Ql[(wm + lr + 8) * AQ + kc]);
                al[2] = __float_as_uint(Ql[(wm + lr) * AQ + kc + 4]);
                al[3] = __float_as_uint(Ql[(wm + lr + 8) * AQ + kc + 4]);
                #pragma unroll
                for (int nj = 0; nj < 4; nj++) {
                    int cn = wnq + nj * 8 + lr;
                    unsigned bh_[2], bl_[2];
                    bh_[0] = __float_as_uint(Khi[cn * AQ + kc]);
                    bh_[1] = __float_as_uint(Khi[cn * AQ + kc + 4]);
                    bl_[0] = __float_as_uint(Klo[cn * AQ + kc]);
                    bl_[1] = __float_as_uint(Klo[cn * AQ + kc + 4]);
                    mma_tf32(cq[nj], ah, bh_);
                    mma_tf32(cq[nj], al, bh_);
                    mma_tf32(cq[nj], ah, bl_);
                }
            }

            #pragma unroll
            for (int nj = 0; nj < 4; nj++) {
                int col = wnq + nj * 8 + 2 * lc;
                int r0 = wm + lr, r1 = wm + lr + 8;
                Ps[r0 * AP + col]     = (k0 + col     <= q0 + r0) ? cq[nj][0] : -1e30f;
                Ps[r0 * AP + col + 1] = (k0 + col + 1 <= q0 + r0) ? cq[nj][1] : -1e30f;
                Ps[r1 * AP + col]     = (k0 + col     <= q0 + r1) ? cq[nj][2] : -1e30f;
                Ps[r1 * AP + col + 1] = (k0 + col + 1 <= q0 + r1) ? cq[nj][3] : -1e30f;
            }
        }
        __syncthreads();

        // Online softmax, both heads
        #pragma unroll
        for (int hh = 0; hh < 2; hh++) {
            float* Ps = hh ? Ph1 : Ph0;
            float* crh = hh ? cr1 : cr0;
            float s[16];
            #pragma unroll
            for (int j4 = 0; j4 < 4; j4++) {
                float4 v4 = *(const float4*)(Ps + myrow * AP + myg * 16 + j4 * 4);
                s[j4 * 4 + 0] = v4.x; s[j4 * 4 + 1] = v4.y;
                s[j4 * 4 + 2] = v4.z; s[j4 * 4 + 3] = v4.w;
            }
            float mx = s[0];
            #pragma unroll
            for (int j = 1; j < 16; j++) mx = fmaxf(mx, s[j]);
            mx = fmaxf(mx, __shfl_xor_sync(0xffffffffu, mx, 1));
            mx = fmaxf(mx, __shfl_xor_sync(0xffffffffu, mx, 2));
            float mnew = fmaxf(mm[hh], mx);
            float corr = __expf(mm[hh] - mnew);
            float rs = 0.f;
            #pragma unroll
            for (int j = 0; j < 16; j++) {
                float p = __expf(s[j] - mnew);
                rs += p;
                Ps[myrow * AP + myg * 16 + j] = tf32_rna(p);
            }
            rs += __shfl_xor_sync(0xffffffffu, rs, 1);
            rs += __shfl_xor_sync(0xffffffffu, rs, 2);
            mm[hh] = mnew;
            ll[hh] = ll[hh] * corr + rs;
            if (myg == 0) crh[myrow] = corr;
        }
        __syncthreads();

        // Rescale + PV, both heads
        #pragma unroll
        for (int hh = 0; hh < 2; hh++) {
            const float* Ps = hh ? Ph1 : Ph0;
            const float* crh = hh ? cr1 : cr0;
            float c0 = crh[wm + lr], c1 = crh[wm + lr + 8];
            #pragma unroll
            for (int nj = 0; nj < 5; nj++) {
                co[hh][nj][0] *= c0; co[hh][nj][1] *= c0;
                co[hh][nj][2] *= c1; co[hh][nj][3] *= c1;
            }
            #pragma unroll
            for (int ks = 0; ks < 8; ks++) {
                const int kc = ks * 8 + lc;
                unsigned a[4];
                a[0] = __float_as_uint(Ps[(wm + lr) * AP + kc]);
                a[1] = __float_as_uint(Ps[(wm + lr + 8) * AP + kc]);
                a[2] = __float_as_uint(Ps[(wm + lr) * AP + kc + 4]);
                a[3] = __float_as_uint(Ps[(wm + lr + 8) * AP + kc + 4]);
                #pragma unroll
                for (int nj = 0; nj < 5; nj++) {
                    int cn = wnp + nj * 8 + lr;
                    unsigned bh_[2], bl_[2];
                    bh_[0] = __float_as_uint(Vhi[(kc)     * AV + cn]);
                    bh_[1] = __float_as_uint(Vhi[(kc + 4) * AV + cn]);
                    bl_[0] = __float_as_uint(Vlo[(kc)     * AV + cn]);
                    bl_[1] = __float_as_uint(Vlo[(kc + 4) * AV + cn]);
                    mma_tf32(co[hh][nj], a, bh_);
                    mma_tf32(co[hh][nj], a, bl_);
                }
            }
        }
    }

    // Epilogue
    __syncthreads();
    if (myg == 0) { cr0[myrow] = 1.f / ll[0]; cr1[myrow] = 1.f / ll[1]; }
    __syncthreads();
    #pragma unroll
    for (int hh = 0; hh < 2; hh++) {
        const float* crh = hh ? cr1 : cr0;
        float i0 = crh[wm + lr], i1 = crh[wm + lr + 8];
        size_t ro0 = ((size_t)(b * S_ + q0 + wm + lr)) * (H_ * D_) + (h0 + hh) * D_;
        size_t ro1 = ((size_t)(b * S_ + q0 + wm + lr + 8)) * (H_ * D_) + (h0 + hh) * D_;
        #pragma unroll
        for (int nj = 0; nj < 5; nj++) {
            int col = wnp + nj * 8 + 2 * lc;
            *(float2*)(O + ro0 + col) =
                make_float2(tf32_rna(co[hh][nj][0] * i0), tf32_rna(co[hh][nj][1] * i0));
            *(float2*)(O + ro1 + col) =
                make_float2(tf32_rna(co[hh][nj][2] * i1), tf32_rna(co[hh][nj][3] * i1));
        }
    }
}

// ---------------------------------------------------------------------------
// Launch
// ---------------------------------------------------------------------------
extern "C" void kernel_launch(void* const* d_in, const int* in_sizes, int n_in,
                              void* d_out, int out_size)
{
    const float* hs   = (const float*)d_in[0];
    const float* cosf = (const float*)d_in[1];
    const float* sinf = (const float*)d_in[2];
    const float* Wq   = (const float*)d_in[3];
    const float* Wk   = (const float*)d_in[4];
    const float* Wv   = (const float*)d_in[5];
    const float* Wo   = (const float*)d_in[6];
    float* out = (float*)d_out;

    float *Qp, *Kp, *Vp, *Cp, *HSr, *Wqr, *Wkr, *Wvr, *Wor;
    cudaGetSymbolAddress((void**)&Qp,  g_Q);
    cudaGetSymbolAddress((void**)&Kp,  g_K);
    cudaGetSymbolAddress((void**)&Vp,  g_V);
    cudaGetSymbolAddress((void**)&Cp,  g_ctx);
    cudaGetSymbolAddress((void**)&HSr, g_hs_r);
    cudaGetSymbolAddress((void**)&Wqr, g_Wq_r);
    cudaGetSymbolAddress((void**)&Wkr, g_Wk_r);
    cudaGetSymbolAddress((void**)&Wvr, g_Wv_r);
    cudaGetSymbolAddress((void**)&Wor, g_Wo_r);

    // TF32 RNA pre-rounding
    {
        auto rnd = [](const float* src, float* dst, size_t n) {
            int n4 = (int)(n / 4);
            round_tf32<<<(n4 + 255) / 256, 256>>>(
                (const float4*)src, (float4*)dst, n4);
        };
        rnd(hs, HSr, (size_t)BS_ * HID_);
        rnd(Wq, Wqr, (size_t)HID_ * H_ * D_);
        rnd(Wk, Wkr, (size_t)HID_ * KV_ * D_);
        rnd(Wv, Wvr, (size_t)HID_ * KV_ * D_);
        rnd(Wo, Wor, (size_t)H_ * D_ * HID_);
    }

    // Fused QKV projection
    {
        dim3 g(30, BS_ / 128);
        gemm_qkv<<<g, 256>>>(HSr, Wqr, Qp, Wkr, Kp, Wvr, Vp);
    }

    // RoPE on Q and K
    {
        size_t tq = (size_t)BS_ * H_ * 40;
        size_t tk = (size_t)BS_ * KV_ * 40;
        rope_kernel<<<(unsigned)((tq + 255) / 256), 256>>>(Qp, cosf, sinf, H_, tq);
        rope_kernel<<<(unsigned)((tk + 255) / 256), 256>>>(Kp, cosf, sinf, KV_, tk);
    }

    // Attention: 2 heads per block, GQA K/V sharing
    {
        const int smem = (6 * 64 * AQ + 2 * 64 * AV + 2 * 64 * AP + 128)
                         * (int)sizeof(float);   // 209,408 B
        cudaFuncSetAttribute(attn_mma2,
                             cudaFuncAttributeMaxDynamicSharedMemorySize, smem);
        dim3 ga(S_ / 64, B_ * KV_ * 2);          // (32, 32)
        attn_mma2<<<ga, 256, smem>>>(Qp, Kp, Vp, Cp);
    }

    // Output projection
    {
        dim3 go(HID_ / 128, BS_ / 128);
        gemm_tf32<<<go, 256>>>(Cp, Wor, out, HID_, HID_);
    }
}